// round 8
// baseline (speedup 1.0000x reference)
#include <cuda_runtime.h>
#include <cuda_bf16.h>
#include <cstdint>

#define TT 1024
#define BB 4
#define DIM 1024
#define NH 16
#define HD 64
#define NTOK (TT * BB)     // 4096 tokens
#define ROWSTR (BB * DIM)  // 4096 elems per t-step

// ---------------- scratch (device globals; no allocations allowed) --------
// pre-split bf16 hi/lo pairs
__device__ __nv_bfloat16 g_xh[NTOK * DIM], g_xl[NTOK * DIM];
__device__ __nv_bfloat16 g_Wqh[DIM * DIM], g_Wql[DIM * DIM];
__device__ __nv_bfloat16 g_Wkh[DIM * DIM], g_Wkl[DIM * DIM];
__device__ __nv_bfloat16 g_Wvh[DIM * DIM], g_Wvl[DIM * DIM];
__device__ __nv_bfloat16 g_Woh[DIM * DIM], g_Wol[DIM * DIM];
__device__ __nv_bfloat16 g_Wlh[DIM * DIM], g_Wll[DIM * DIM];
__device__ __nv_bfloat16 g_qh[NTOK * DIM], g_ql[NTOK * DIM];
__device__ __nv_bfloat16 g_kh[NTOK * DIM], g_kl[NTOK * DIM];
__device__ __nv_bfloat16 g_vh[NTOK * DIM], g_vl[NTOK * DIM];
__device__ __nv_bfloat16 g_ch[NTOK * DIM], g_cl[NTOK * DIM];
__device__ __nv_bfloat16 g_hh[NTOK * DIM], g_hl[NTOK * DIM];
// fp32 intermediates
__device__ float g_t1[NTOK * DIM];
__device__ float g_hf[NTOK * DIM];
__device__ float g_t2[NTOK * DIM];

// ===========================================================================
// helpers
// ===========================================================================
__device__ __forceinline__ void mma16816(float* c, const uint32_t* a,
                                         const uint32_t* b) {
    asm volatile(
        "mma.sync.aligned.m16n8k16.row.col.f32.bf16.bf16.f32 "
        "{%0,%1,%2,%3}, {%4,%5,%6,%7}, {%8,%9}, {%0,%1,%2,%3};"
        : "+f"(c[0]), "+f"(c[1]), "+f"(c[2]), "+f"(c[3])
        : "r"(a[0]), "r"(a[1]), "r"(a[2]), "r"(a[3]), "r"(b[0]), "r"(b[1]));
}

__device__ __forceinline__ uint32_t pack_hi(float v0, float v1, float& l0,
                                            float& l1) {
    __nv_bfloat16 h0 = __float2bfloat16_rn(v0);
    __nv_bfloat16 h1 = __float2bfloat16_rn(v1);
    l0 = v0 - __bfloat162float(h0);
    l1 = v1 - __bfloat162float(h1);
    __nv_bfloat162 p;
    p.x = h0; p.y = h1;
    return *(uint32_t*)&p;
}

__device__ __forceinline__ uint32_t pack2(float v0, float v1) {
    __nv_bfloat162 p;
    p.x = __float2bfloat16_rn(v0);
    p.y = __float2bfloat16_rn(v1);
    return *(uint32_t*)&p;
}

// ===========================================================================
// split prep: fp32 -> bf16 hi/lo (grid-stride over float4s)
// ===========================================================================
__global__ __launch_bounds__(256)
void split_kernel(const float* __restrict__ src, __nv_bfloat16* __restrict__ dh,
                  __nv_bfloat16* __restrict__ dl, int n4) {
    int i = blockIdx.x * blockDim.x + threadIdx.x;
    const int stride = gridDim.x * blockDim.x;
    for (; i < n4; i += stride) {
        float4 f = ((const float4*)src)[i];
        float l0, l1, l2, l3;
        uint2 uh, ul;
        uh.x = pack_hi(f.x, f.y, l0, l1);
        uh.y = pack_hi(f.z, f.w, l2, l3);
        ul.x = pack2(l0, l1);
        ul.y = pack2(l2, l3);
        ((uint2*)dh)[i] = uh;
        ((uint2*)dl)[i] = ul;
    }
}

// ===========================================================================
// GEMM on pre-split bf16 operands. C = A @ W^T + bias.
// 128x128 tile, BK=32, 8 warps (2x4), double-buffered, no in-loop conversion.
// MODE 0: fp32 C out.  MODE 1: bf16 hi/lo C out.
// ===========================================================================
#define TILEB (128 * 80)         // 10240 B per padded 128x32 bf16 tile
#define STAGEB (4 * TILEB)
#define GEMM_SMEM (2 * STAGEB)   // 81920 B

template <int MODE>
__device__ __forceinline__ void gemm_body_bf(
    const __nv_bfloat16* __restrict__ Ah, const __nv_bfloat16* __restrict__ Al,
    const __nv_bfloat16* __restrict__ Bh, const __nv_bfloat16* __restrict__ Bl,
    const float* __restrict__ bias, float* __restrict__ Cf,
    __nv_bfloat16* __restrict__ Ch, __nv_bfloat16* __restrict__ Cl, char* sm) {
    const int tid = threadIdx.x;
    const int wid = tid >> 5;
    const int lane = tid & 31;
    const int laneR = lane >> 2;
    const int laneC = lane & 3;
    const int mBase = (wid >> 2) * 64;
    const int nBase = (wid & 3) * 32;
    const int m0 = blockIdx.y * 128;
    const int n0 = blockIdx.x * 128;

    // loader: 128 rows x 4 groups of 8 bf16 (16B) per tile; 512 tasks; 2 its
    const int lrow = tid >> 2;          // base row (0..63), +64 for it=1
    const int lg16 = (tid & 3) * 16;    // byte group in row
    const int lcol = (tid & 3) * 8;     // elem col

    float acc[4][4][4];
#pragma unroll
    for (int i = 0; i < 4; i++)
#pragma unroll
        for (int j = 0; j < 4; j++)
#pragma unroll
            for (int r = 0; r < 4; r++) acc[i][j][r] = 0.f;

    uint4 rah[2], ral[2], rbh[2], rbl[2];

    auto load_g = [&](int ch) {
        const int k0 = ch * 32;
#pragma unroll
        for (int it = 0; it < 2; it++) {
            int row = lrow + it * 64;
            size_t ao = (size_t)(m0 + row) * DIM + k0 + lcol;
            size_t bo = (size_t)(n0 + row) * DIM + k0 + lcol;
            rah[it] = *(const uint4*)(Ah + ao);
            ral[it] = *(const uint4*)(Al + ao);
            rbh[it] = *(const uint4*)(Bh + bo);
            rbl[it] = *(const uint4*)(Bl + bo);
        }
    };

    auto sts = [&](int b) {
        char* st = sm + b * STAGEB;
#pragma unroll
        for (int it = 0; it < 2; it++) {
            int row = lrow + it * 64;
            uint32_t off = row * 80 + lg16;
            *(uint4*)(st + off) = rah[it];
            *(uint4*)(st + TILEB + off) = ral[it];
            *(uint4*)(st + 2 * TILEB + off) = rbh[it];
            *(uint4*)(st + 3 * TILEB + off) = rbl[it];
        }
    };

    auto mma_stage = [&](int b) {
        const char* sb = sm + b * STAGEB;
#pragma unroll
        for (int s = 0; s < 2; s++) {
            const uint32_t so = s * 32 + laneC * 4;
            uint32_t bh[4][2], bl[4][2];
#pragma unroll
            for (int tj = 0; tj < 4; tj++) {
                uint32_t r = (nBase + tj * 8 + laneR) * 80 + so;
                bh[tj][0] = *(const uint32_t*)(sb + 2 * TILEB + r);
                bh[tj][1] = *(const uint32_t*)(sb + 2 * TILEB + r + 16);
                bl[tj][0] = *(const uint32_t*)(sb + 3 * TILEB + r);
                bl[tj][1] = *(const uint32_t*)(sb + 3 * TILEB + r + 16);
            }
#pragma unroll
            for (int ti = 0; ti < 4; ti++) {
                uint32_t r = (mBase + ti * 16 + laneR) * 80 + so;
                uint32_t ah[4], al[4];
                ah[0] = *(const uint32_t*)(sb + r);
                ah[1] = *(const uint32_t*)(sb + r + 640);
                ah[2] = *(const uint32_t*)(sb + r + 16);
                ah[3] = *(const uint32_t*)(sb + r + 656);
                al[0] = *(const uint32_t*)(sb + TILEB + r);
                al[1] = *(const uint32_t*)(sb + TILEB + r + 640);
                al[2] = *(const uint32_t*)(sb + TILEB + r + 16);
                al[3] = *(const uint32_t*)(sb + TILEB + r + 656);
#pragma unroll
                for (int tj = 0; tj < 4; tj++) {
                    mma16816(acc[ti][tj], ah, bh[tj]);
                    mma16816(acc[ti][tj], ah, bl[tj]);
                    mma16816(acc[ti][tj], al, bh[tj]);
                }
            }
        }
    };

    load_g(0);
    sts(0);
    __syncthreads();

    for (int ch = 0; ch < 32; ch++) {
        const int b = ch & 1;
        if (ch < 31) load_g(ch + 1);
        mma_stage(b);
        if (ch < 31) sts(b ^ 1);
        __syncthreads();
    }

#pragma unroll
    for (int ti = 0; ti < 4; ti++) {
        const int row = m0 + mBase + ti * 16 + laneR;
#pragma unroll
        for (int tj = 0; tj < 4; tj++) {
            const int col = n0 + nBase + tj * 8 + laneC * 2;
            const float b0 = __ldg(bias + col);
            const float b1 = __ldg(bias + col + 1);
            float c00 = acc[ti][tj][0] + b0, c01 = acc[ti][tj][1] + b1;
            float c10 = acc[ti][tj][2] + b0, c11 = acc[ti][tj][3] + b1;
            if (MODE == 0) {
                *(float2*)(Cf + (size_t)row * DIM + col) = make_float2(c00, c01);
                *(float2*)(Cf + (size_t)(row + 8) * DIM + col) =
                    make_float2(c10, c11);
            } else {
                float l0, l1;
                uint32_t uh = pack_hi(c00, c01, l0, l1);
                *(uint32_t*)(Ch + (size_t)row * DIM + col) = uh;
                *(uint32_t*)(Cl + (size_t)row * DIM + col) = pack2(l0, l1);
                uh = pack_hi(c10, c11, l0, l1);
                *(uint32_t*)(Ch + (size_t)(row + 8) * DIM + col) = uh;
                *(uint32_t*)(Cl + (size_t)(row + 8) * DIM + col) = pack2(l0, l1);
            }
        }
    }
}

__global__ __launch_bounds__(256, 1)
void gemm_bf_f32(const __nv_bfloat16* Ah, const __nv_bfloat16* Al,
                 const __nv_bfloat16* Bh, const __nv_bfloat16* Bl,
                 const float* bias, float* Cf) {
    extern __shared__ char sm[];
    gemm_body_bf<0>(Ah, Al, Bh, Bl, bias, Cf, nullptr, nullptr, sm);
}

// batched QKV: grid.z selects weights/bias/outputs; bf16 hi/lo outputs
__global__ __launch_bounds__(256, 1)
void gemm_bf_qkv(const __nv_bfloat16* Ah, const __nv_bfloat16* Al,
                 const float* bq, const float* bk, const float* bv) {
    extern __shared__ char sm[];
    const int z = blockIdx.z;
    const __nv_bfloat16* Bh = (z == 0) ? g_Wqh : (z == 1) ? g_Wkh : g_Wvh;
    const __nv_bfloat16* Bl = (z == 0) ? g_Wql : (z == 1) ? g_Wkl : g_Wvl;
    const float* bias = (z == 0) ? bq : (z == 1) ? bk : bv;
    __nv_bfloat16* Ch = (z == 0) ? g_qh : (z == 1) ? g_kh : g_vh;
    __nv_bfloat16* Cl = (z == 0) ? g_ql : (z == 1) ? g_kl : g_vl;
    gemm_body_bf<1>(Ah, Al, Bh, Bl, bias, nullptr, Ch, Cl, sm);
}

// ===========================================================================
// Attention: FA2-style mma.sync bf16 split, pre-split bf16 inputs/outputs.
// Block: one (b,h) x 128 queries. 8 warps; warp owns 16 query rows.
// ===========================================================================
#define SQH 0
#define SQL 18432
#define SKH 36864
#define SKL 55296
#define SVH 73728
#define SVL 91392
#define ATT_SMEM 109056
#define QKSTR 144
#define VTSTR 276

__global__ __launch_bounds__(256, 1)
void attn_mma_kernel(const __nv_bfloat16* __restrict__ qh,
                     const __nv_bfloat16* __restrict__ ql,
                     const __nv_bfloat16* __restrict__ kh,
                     const __nv_bfloat16* __restrict__ kl,
                     const __nv_bfloat16* __restrict__ vh,
                     const __nv_bfloat16* __restrict__ vl,
                     __nv_bfloat16* __restrict__ ch,
                     __nv_bfloat16* __restrict__ cl) {
    extern __shared__ char smc[];
    const int tid = threadIdx.x;
    const int wid = tid >> 5;
    const int lane = tid & 31;
    const int laneR = lane >> 2;
    const int laneC = lane & 3;
    const int b = blockIdx.x >> 4;
    const int h = blockIdx.x & 15;
    const int t0 = blockIdx.y * 128;
    const size_t base = (size_t)b * DIM + h * HD;
    const int mrow = wid * 16;

    // ---- load Q tiles (hi/lo): 128 rows x 8 groups of 8 bf16, per tile ----
#pragma unroll
    for (int it = 0; it < 8; it++) {
        int task = tid + it * 256;      // 0..2047
        int tile = task >> 10;          // 0: hi, 1: lo
        int tt = task & 1023;
        int row = tt >> 3;
        int g = (tt & 7) * 8;
        const __nv_bfloat16* src = tile ? ql : qh;
        uint4 u = *(const uint4*)(src + (size_t)(t0 + row) * ROWSTR + base + g);
        *(uint4*)(smc + (tile ? SQL : SQH) + row * QKSTR + g * 2) = u;
    }

    float oacc[8][4];
#pragma unroll
    for (int i = 0; i < 8; i++)
#pragma unroll
        for (int r = 0; r < 4; r++) oacc[i][r] = 0.f;
    float mr[2] = {-1e30f, -1e30f};
    float ls[2] = {0.f, 0.f};

    for (int kt = 0; kt < 8; kt++) {
        const int s0 = kt * 128;
        __syncthreads();

        // ---- K tiles ----
#pragma unroll
        for (int it = 0; it < 8; it++) {
            int task = tid + it * 256;
            int tile = task >> 10;
            int tt = task & 1023;
            int row = tt >> 3;
            int g = (tt & 7) * 8;
            const __nv_bfloat16* src = tile ? kl : kh;
            uint4 u =
                *(const uint4*)(src + (size_t)(s0 + row) * ROWSTR + base + g);
            *(uint4*)(smc + (tile ? SKL : SKH) + row * QKSTR + g * 2) = u;
        }

        // ---- V transposed tiles: Vt[d][sp] = (v[2sp][d], v[2sp+1][d]) ----
#pragma unroll
        for (int it = 0; it < 4; it++) {
            int task = tid + it * 256;  // 0..1023
            int tile = task >> 9;       // 0: hi, 1: lo
            int tt = task & 511;
            int sp = tt >> 3;           // key pair 0..63
            int d0 = (tt & 7) * 8;      // 0..56
            const __nv_bfloat16* src = tile ? vl : vh;
            const __nv_bfloat16* p0 =
                src + (size_t)(s0 + 2 * sp) * ROWSTR + base + d0;
            uint4 u0 = *(const uint4*)p0;
            uint4 u1 = *(const uint4*)(p0 + ROWSTR);
            char* dst = smc + (tile ? SVL : SVH) + sp * 4;
            uint32_t a0[4] = {u0.x, u0.y, u0.z, u0.w};
            uint32_t a1[4] = {u1.x, u1.y, u1.z, u1.w};
#pragma unroll
            for (int w = 0; w < 4; w++) {
                *(uint32_t*)(dst + (d0 + 2 * w) * VTSTR) =
                    __byte_perm(a0[w], a1[w], 0x5410);
                *(uint32_t*)(dst + (d0 + 2 * w + 1) * VTSTR) =
                    __byte_perm(a0[w], a1[w], 0x7632);
            }
        }
        __syncthreads();

        // ---- S = Q K^T (16 rows x 128 keys), 3-pass split ----
        float sacc[16][4];
#pragma unroll
        for (int nt = 0; nt < 16; nt++)
#pragma unroll
            for (int r = 0; r < 4; r++) sacc[nt][r] = 0.f;

#pragma unroll
        for (int ks = 0; ks < 4; ks++) {
            const uint32_t qb = (mrow + laneR) * QKSTR + ks * 32 + laneC * 4;
            uint32_t ah[4], al[4];
            ah[0] = *(const uint32_t*)(smc + SQH + qb);
            ah[1] = *(const uint32_t*)(smc + SQH + qb + 8 * QKSTR);
            ah[2] = *(const uint32_t*)(smc + SQH + qb + 16);
            ah[3] = *(const uint32_t*)(smc + SQH + qb + 8 * QKSTR + 16);
            al[0] = *(const uint32_t*)(smc + SQL + qb);
            al[1] = *(const uint32_t*)(smc + SQL + qb + 8 * QKSTR);
            al[2] = *(const uint32_t*)(smc + SQL + qb + 16);
            al[3] = *(const uint32_t*)(smc + SQL + qb + 8 * QKSTR + 16);
#pragma unroll
            for (int nt = 0; nt < 16; nt++) {
                const uint32_t kb =
                    (nt * 8 + laneR) * QKSTR + ks * 32 + laneC * 4;
                uint32_t bhf[2], blf[2];
                bhf[0] = *(const uint32_t*)(smc + SKH + kb);
                bhf[1] = *(const uint32_t*)(smc + SKH + kb + 16);
                blf[0] = *(const uint32_t*)(smc + SKL + kb);
                blf[1] = *(const uint32_t*)(smc + SKL + kb + 16);
                mma16816(sacc[nt], ah, bhf);
                mma16816(sacc[nt], ah, blf);
                mma16816(sacc[nt], al, bhf);
            }
        }

        // ---- online softmax ----
#pragma unroll
        for (int r = 0; r < 2; r++) {
            float mt = -1e30f;
#pragma unroll
            for (int nt = 0; nt < 16; nt++)
                mt = fmaxf(mt, fmaxf(sacc[nt][2 * r], sacc[nt][2 * r + 1]));
            mt = fmaxf(mt, __shfl_xor_sync(0xffffffffu, mt, 1));
            mt = fmaxf(mt, __shfl_xor_sync(0xffffffffu, mt, 2));
            float mnew = fmaxf(mr[r], mt);
            float corr = __expf((mr[r] - mnew) * 0.125f);
            mr[r] = mnew;
            const float mm = mnew * 0.125f;
            float rs = 0.f;
#pragma unroll
            for (int nt = 0; nt < 16; nt++) {
                float p0 = __expf(fmaf(sacc[nt][2 * r], 0.125f, -mm));
                float p1 = __expf(fmaf(sacc[nt][2 * r + 1], 0.125f, -mm));
                sacc[nt][2 * r] = p0;
                sacc[nt][2 * r + 1] = p1;
                rs += p0 + p1;
            }
            rs += __shfl_xor_sync(0xffffffffu, rs, 1);
            rs += __shfl_xor_sync(0xffffffffu, rs, 2);
            ls[r] = ls[r] * corr + rs;
#pragma unroll
            for (int nt2 = 0; nt2 < 8; nt2++) {
                oacc[nt2][2 * r] *= corr;
                oacc[nt2][2 * r + 1] *= corr;
            }
        }

        // ---- O += P @ V (P split in registers) ----
#pragma unroll
        for (int j = 0; j < 8; j++) {
            uint32_t ph[4], pl[4];
            float l0, l1;
            ph[0] = pack_hi(sacc[2 * j][0], sacc[2 * j][1], l0, l1);
            pl[0] = pack2(l0, l1);
            ph[1] = pack_hi(sacc[2 * j][2], sacc[2 * j][3], l0, l1);
            pl[1] = pack2(l0, l1);
            ph[2] = pack_hi(sacc[2 * j + 1][0], sacc[2 * j + 1][1], l0, l1);
            pl[2] = pack2(l0, l1);
            ph[3] = pack_hi(sacc[2 * j + 1][2], sacc[2 * j + 1][3], l0, l1);
            pl[3] = pack2(l0, l1);
#pragma unroll
            for (int nt2 = 0; nt2 < 8; nt2++) {
                const uint32_t vb =
                    (nt2 * 8 + laneR) * VTSTR + j * 32 + laneC * 4;
                uint32_t vhf[2], vlf[2];
                vhf[0] = *(const uint32_t*)(smc + SVH + vb);
                vhf[1] = *(const uint32_t*)(smc + SVH + vb + 16);
                vlf[0] = *(const uint32_t*)(smc + SVL + vb);
                vlf[1] = *(const uint32_t*)(smc + SVL + vb + 16);
                mma16816(oacc[nt2], ph, vhf);
                mma16816(oacc[nt2], ph, vlf);
                mma16816(oacc[nt2], pl, vhf);
            }
        }
    }

    // ---- normalize, split, store bf16 hi/lo ----
    const float inv0 = 1.f / ls[0];
    const float inv1 = 1.f / ls[1];
    const int r0 = t0 + mrow + laneR;
#pragma unroll
    for (int nt2 = 0; nt2 < 8; nt2++) {
        const size_t col = base + nt2 * 8 + laneC * 2;
        float l0, l1;
        uint32_t uh = pack_hi(oacc[nt2][0] * inv0, oacc[nt2][1] * inv0, l0, l1);
        *(uint32_t*)(ch + (size_t)r0 * ROWSTR + col) = uh;
        *(uint32_t*)(cl + (size_t)r0 * ROWSTR + col) = pack2(l0, l1);
        uh = pack_hi(oacc[nt2][2] * inv1, oacc[nt2][3] * inv1, l0, l1);
        *(uint32_t*)(ch + (size_t)(r0 + 8) * ROWSTR + col) = uh;
        *(uint32_t*)(cl + (size_t)(r0 + 8) * ROWSTR + col) = pack2(l0, l1);
    }
}

// ===========================================================================
// Fused residual-add + LayerNorm. SPLIT=1 also emits bf16 hi/lo of the output.
// ===========================================================================
template <int SPLIT>
__device__ __forceinline__ void ln_body(const float* __restrict__ a,
                                        const float* __restrict__ res,
                                        const float* __restrict__ gma,
                                        const float* __restrict__ bta,
                                        float* __restrict__ out,
                                        __nv_bfloat16* __restrict__ oh,
                                        __nv_bfloat16* __restrict__ ol) {
    __shared__ float red[16];
    const int row = blockIdx.x;
    const int tid = threadIdx.x;

    float4 va = *(const float4*)(a + (size_t)row * DIM + tid * 4);
    float4 vr = *(const float4*)(res + (size_t)row * DIM + tid * 4);
    float4 x;
    x.x = va.x + vr.x; x.y = va.y + vr.y; x.z = va.z + vr.z; x.w = va.w + vr.w;

    float sum = x.x + x.y + x.z + x.w;
    float sq = x.x * x.x + x.y * x.y + x.z * x.z + x.w * x.w;
#pragma unroll
    for (int d = 16; d; d >>= 1) {
        sum += __shfl_xor_sync(0xffffffffu, sum, d);
        sq += __shfl_xor_sync(0xffffffffu, sq, d);
    }
    const int warp = tid >> 5;
    if ((tid & 31) == 0) { red[warp] = sum; red[8 + warp] = sq; }
    __syncthreads();
    if (tid < 32) {
        float s = (tid < 8) ? red[tid] : 0.f;
        float q2 = (tid < 8) ? red[8 + tid] : 0.f;
#pragma unroll
        for (int d = 4; d; d >>= 1) {
            s += __shfl_xor_sync(0xffffffffu, s, d);
            q2 += __shfl_xor_sync(0xffffffffu, q2, d);
        }
        if (tid == 0) { red[0] = s; red[1] = q2; }
    }
    __syncthreads();
    const float mean = red[0] * (1.f / DIM);
    const float var = red[1] * (1.f / DIM) - mean * mean;
    const float rstd = rsqrtf(var + 1e-5f);

    float4 g4 = *(const float4*)(gma + tid * 4);
    float4 b4 = *(const float4*)(bta + tid * 4);
    float4 o;
    o.x = (x.x - mean) * rstd * g4.x + b4.x;
    o.y = (x.y - mean) * rstd * g4.y + b4.y;
    o.z = (x.z - mean) * rstd * g4.z + b4.z;
    o.w = (x.w - mean) * rstd * g4.w + b4.w;
    *(float4*)(out + (size_t)row * DIM + tid * 4) = o;
    if (SPLIT) {
        float l0, l1, l2, l3;
        uint2 uh, ul;
        uh.x = pack_hi(o.x, o.y, l0, l1);
        uh.y = pack_hi(o.z, o.w, l2, l3);
        ul.x = pack2(l0, l1);
        ul.y = pack2(l2, l3);
        *(uint2*)(oh + (size_t)row * DIM + tid * 4) = uh;
        *(uint2*)(ol + (size_t)row * DIM + tid * 4) = ul;
    }
}

__global__ __launch_bounds__(256)
void add_ln_kernel(const float* a, const float* res, const float* gma,
                   const float* bta, float* out) {
    ln_body<0>(a, res, gma, bta, out, nullptr, nullptr);
}

__global__ __launch_bounds__(256)
void add_ln_split_kernel(const float* a, const float* res, const float* gma,
                         const float* bta, float* out, __nv_bfloat16* oh,
                         __nv_bfloat16* ol) {
    ln_body<1>(a, res, gma, bta, out, oh, ol);
}

// ===========================================================================
// launch
// ===========================================================================
extern "C" void kernel_launch(void* const* d_in, const int* in_sizes, int n_in,
                              void* d_out, int out_size) {
    const float* x  = (const float*)d_in[0];
    const float* Wq = (const float*)d_in[1];
    const float* bq = (const float*)d_in[2];
    const float* Wk = (const float*)d_in[3];
    const float* bk = (const float*)d_in[4];
    const float* Wv = (const float*)d_in[5];
    const float* bv = (const float*)d_in[6];
    const float* Wo = (const float*)d_in[7];
    const float* bo = (const float*)d_in[8];
    const float* Wl = (const float*)d_in[9];
    const float* bl = (const float*)d_in[10];
    const float* g1 = (const float*)d_in[11];
    const float* b1 = (const float*)d_in[12];
    const float* g2 = (const float*)d_in[13];
    const float* b2 = (const float*)d_in[14];
    float* out = (float*)d_out;

    __nv_bfloat16 *xh, *xl, *Wqh, *Wql, *Wkh, *Wkl, *Wvh, *Wvl, *Woh, *Wol,
        *Wlh, *Wll, *qh, *ql, *kh, *kl, *vh, *vl, *chp, *clp, *hh, *hl;
    float *t1, *hf, *t2;
    cudaGetSymbolAddress((void**)&xh, g_xh);
    cudaGetSymbolAddress((void**)&xl, g_xl);
    cudaGetSymbolAddress((void**)&Wqh, g_Wqh);
    cudaGetSymbolAddress((void**)&Wql, g_Wql);
    cudaGetSymbolAddress((void**)&Wkh, g_Wkh);
    cudaGetSymbolAddress((void**)&Wkl, g_Wkl);
    cudaGetSymbolAddress((void**)&Wvh, g_Wvh);
    cudaGetSymbolAddress((void**)&Wvl, g_Wvl);
    cudaGetSymbolAddress((void**)&Woh, g_Woh);
    cudaGetSymbolAddress((void**)&Wol, g_Wol);
    cudaGetSymbolAddress((void**)&Wlh, g_Wlh);
    cudaGetSymbolAddress((void**)&Wll, g_Wll);
    cudaGetSymbolAddress((void**)&qh, g_qh);
    cudaGetSymbolAddress((void**)&ql, g_ql);
    cudaGetSymbolAddress((void**)&kh, g_kh);
    cudaGetSymbolAddress((void**)&kl, g_kl);
    cudaGetSymbolAddress((void**)&vh, g_vh);
    cudaGetSymbolAddress((void**)&vl, g_vl);
    cudaGetSymbolAddress((void**)&chp, g_ch);
    cudaGetSymbolAddress((void**)&clp, g_cl);
    cudaGetSymbolAddress((void**)&hh, g_hh);
    cudaGetSymbolAddress((void**)&hl, g_hl);
    cudaGetSymbolAddress((void**)&t1, g_t1);
    cudaGetSymbolAddress((void**)&hf, g_hf);
    cudaGetSymbolAddress((void**)&t2, g_t2);

    cudaFuncSetAttribute(attn_mma_kernel,
                         cudaFuncAttributeMaxDynamicSharedMemorySize, ATT_SMEM);
    cudaFuncSetAttribute(gemm_bf_f32,
                         cudaFuncAttributeMaxDynamicSharedMemorySize, GEMM_SMEM);
    cudaFuncSetAttribute(gemm_bf_qkv,
                         cudaFuncAttributeMaxDynamicSharedMemorySize, GEMM_SMEM);

    // prep: split x + 5 weights into bf16 hi/lo
    split_kernel<<<2048, 256>>>(x, xh, xl, NTOK * DIM / 4);
    split_kernel<<<1024, 256>>>(Wq, Wqh, Wql, DIM * DIM / 4);
    split_kernel<<<1024, 256>>>(Wk, Wkh, Wkl, DIM * DIM / 4);
    split_kernel<<<1024, 256>>>(Wv, Wvh, Wvl, DIM * DIM / 4);
    split_kernel<<<1024, 256>>>(Wo, Woh, Wol, DIM * DIM / 4);
    split_kernel<<<1024, 256>>>(Wl, Wlh, Wll, DIM * DIM / 4);

    dim3 ggrid(DIM / 128, NTOK / 128);      // (8, 32)
    dim3 ggrid3(DIM / 128, NTOK / 128, 3);  // QKV batched
    dim3 gblk(256);

    gemm_bf_qkv<<<ggrid3, gblk, GEMM_SMEM>>>(xh, xl, bq, bk, bv);
    attn_mma_kernel<<<dim3(BB * NH, TT / 128), 256, ATT_SMEM>>>(
        qh, ql, kh, kl, vh, vl, chp, clp);
    gemm_bf_f32<<<ggrid, gblk, GEMM_SMEM>>>(chp, clp, Woh, Wol, bo, t1);
    add_ln_split_kernel<<<NTOK, 256>>>(t1, x, g1, b1, hf, hh, hl);
    gemm_bf_f32<<<ggrid, gblk, GEMM_SMEM>>>(hh, hl, Wlh, Wll, bl, t2);
    add_ln_kernel<<<NTOK, 256>>>(t2, hf, g2, b2, out);
}

// round 14
// speedup vs baseline: 1.0669x; 1.0669x over previous
#include <cuda_runtime.h>
#include <cuda_bf16.h>
#include <cstdint>

#define TT 1024
#define BB 4
#define DIM 1024
#define NH 16
#define HD 64
#define NTOK (TT * BB)     // 4096 tokens
#define ROWSTR (BB * DIM)  // 4096 floats per t-step

// ---------------- scratch (device globals; no allocations allowed) --------
__device__ float g_q[NTOK * DIM];
__device__ float g_k[NTOK * DIM];
__device__ float g_v[NTOK * DIM];
__device__ float g_ctx[NTOK * DIM];
__device__ float g_t1[NTOK * DIM];
__device__ float g_h[NTOK * DIM];
__device__ float g_t2[NTOK * DIM];

// ===========================================================================
// helpers
// ===========================================================================
__device__ __forceinline__ void mma16816(float* c, const uint32_t* a,
                                         const uint32_t* b) {
    asm volatile(
        "mma.sync.aligned.m16n8k16.row.col.f32.bf16.bf16.f32 "
        "{%0,%1,%2,%3}, {%4,%5,%6,%7}, {%8,%9}, {%0,%1,%2,%3};"
        : "+f"(c[0]), "+f"(c[1]), "+f"(c[2]), "+f"(c[3])
        : "r"(a[0]), "r"(a[1]), "r"(a[2]), "r"(a[3]), "r"(b[0]), "r"(b[1]));
}

__device__ __forceinline__ void ldsm4(uint32_t* r, uint32_t addr) {
    asm volatile(
        "ldmatrix.sync.aligned.m8n8.x4.shared.b16 {%0,%1,%2,%3}, [%4];"
        : "=r"(r[0]), "=r"(r[1]), "=r"(r[2]), "=r"(r[3]) : "r"(addr));
}

__device__ __forceinline__ void ldsm2(uint32_t* r, uint32_t addr) {
    asm volatile("ldmatrix.sync.aligned.m8n8.x2.shared.b16 {%0,%1}, [%2];"
                 : "=r"(r[0]), "=r"(r[1]) : "r"(addr));
}

__device__ __forceinline__ uint32_t s2u(const void* p) {
    return (uint32_t)__cvta_generic_to_shared(p);
}

__device__ __forceinline__ uint32_t pack_hi(float v0, float v1, float& l0,
                                            float& l1) {
    __nv_bfloat16 h0 = __float2bfloat16_rn(v0);
    __nv_bfloat16 h1 = __float2bfloat16_rn(v1);
    l0 = v0 - __bfloat162float(h0);
    l1 = v1 - __bfloat162float(h1);
    __nv_bfloat162 p;
    p.x = h0; p.y = h1;
    return *(uint32_t*)&p;
}

__device__ __forceinline__ uint32_t pack2(float v0, float v1) {
    __nv_bfloat162 p;
    p.x = __float2bfloat16_rn(v0);
    p.y = __float2bfloat16_rn(v1);
    return *(uint32_t*)&p;
}

// ===========================================================================
// GEMM via mma.sync bf16 2-term split (3 passes), ldmatrix fragment loads.
// C[4096,1024] = A @ W^T + bias. 128x128 tile, BK=32, 8 warps, double buffer.
// ===========================================================================
#define TILEB (128 * 80)
#define STAGEB (4 * TILEB)
#define GEMM_SMEM (2 * STAGEB)

__device__ __forceinline__ void gemm_body(const float* __restrict__ A,
                                          const float* __restrict__ W,
                                          const float* __restrict__ bias,
                                          float* __restrict__ C, char* sm) {
    const int tid = threadIdx.x;
    const int wid = tid >> 5;
    const int lane = tid & 31;
    const int laneR = lane >> 2;
    const int laneC = lane & 3;
    const int mBase = (wid >> 2) * 64;
    const int nBase = (wid & 3) * 32;
    const int m0 = blockIdx.y * 128;
    const int n0 = blockIdx.x * 128;

    const int lrow = tid >> 3;
    const int lc4 = (tid & 7) << 2;

    // ldmatrix lane->address components (strides multiple of 16B: OK)
    const int g8 = lane >> 3;
    const int lr8 = lane & 7;
    const uint32_t aoff = (uint32_t)((mBase + (g8 & 1) * 8 + lr8) * 80 +
                                     (g8 >> 1) * 16);
    const uint32_t boff = (uint32_t)((nBase + lr8) * 80 + (g8 & 1) * 16);

    float acc[4][4][4];
#pragma unroll
    for (int i = 0; i < 4; i++)
#pragma unroll
        for (int j = 0; j < 4; j++)
#pragma unroll
            for (int r = 0; r < 4; r++) acc[i][j][r] = 0.f;

    float4 ra[4], rb[4];

    auto load_g = [&](int ch) {
        const int k0 = ch * 32;
#pragma unroll
        for (int it = 0; it < 4; it++) {
            int row = lrow + it * 32;
            ra[it] = *(const float4*)(A + (size_t)(m0 + row) * DIM + k0 + lc4);
            rb[it] = *(const float4*)(W + (size_t)(n0 + row) * DIM + k0 + lc4);
        }
    };

    auto cvt_store = [&](int b) {
        char* st = sm + b * STAGEB;
#pragma unroll
        for (int it = 0; it < 4; it++) {
            int row = lrow + it * 32;
            uint32_t bo = row * 80 + lc4 * 2;
            float l0, l1, l2, l3;
            uint2 uh, ul;
            uh.x = pack_hi(ra[it].x, ra[it].y, l0, l1);
            uh.y = pack_hi(ra[it].z, ra[it].w, l2, l3);
            ul.x = pack2(l0, l1);
            ul.y = pack2(l2, l3);
            *(uint2*)(st + bo) = uh;
            *(uint2*)(st + TILEB + bo) = ul;
            uh.x = pack_hi(rb[it].x, rb[it].y, l0, l1);
            uh.y = pack_hi(rb[it].z, rb[it].w, l2, l3);
            ul.x = pack2(l0, l1);
            ul.y = pack2(l2, l3);
            *(uint2*)(st + 2 * TILEB + bo) = uh;
            *(uint2*)(st + 3 * TILEB + bo) = ul;
        }
    };

    auto mma_stage = [&](int b) {
        const uint32_t sbU = s2u(sm + b * STAGEB);
#pragma unroll
        for (int s = 0; s < 2; s++) {
            const uint32_t so = s * 32;
            uint32_t bh[4][2], bl[4][2];
#pragma unroll
            for (int tj = 0; tj < 4; tj++) {
                uint32_t ba = sbU + 2 * TILEB + boff + tj * (8 * 80) + so;
                ldsm2(bh[tj], ba);
                ldsm2(bl[tj], ba + TILEB);
            }
#pragma unroll
            for (int ti = 0; ti < 4; ti++) {
                uint32_t aa = sbU + aoff + ti * (16 * 80) + so;
                uint32_t ah[4], al[4];
                ldsm4(ah, aa);
                ldsm4(al, aa + TILEB);
#pragma unroll
                for (int tj = 0; tj < 4; tj++) {
                    mma16816(acc[ti][tj], ah, bh[tj]);
                    mma16816(acc[ti][tj], ah, bl[tj]);
                    mma16816(acc[ti][tj], al, bh[tj]);
                }
            }
        }
    };

    load_g(0);
    cvt_store(0);
    __syncthreads();

    for (int ch = 0; ch < 32; ch++) {
        const int b = ch & 1;
        if (ch < 31) load_g(ch + 1);
        mma_stage(b);
        if (ch < 31) cvt_store(b ^ 1);
        __syncthreads();
    }

#pragma unroll
    for (int ti = 0; ti < 4; ti++) {
        const int row = m0 + mBase + ti * 16 + laneR;
#pragma unroll
        for (int tj = 0; tj < 4; tj++) {
            const int col = n0 + nBase + tj * 8 + laneC * 2;
            const float b0 = __ldg(bias + col);
            const float b1 = __ldg(bias + col + 1);
            float2 o0 = make_float2(acc[ti][tj][0] + b0, acc[ti][tj][1] + b1);
            float2 o1 = make_float2(acc[ti][tj][2] + b0, acc[ti][tj][3] + b1);
            *(float2*)(C + (size_t)row * DIM + col) = o0;
            *(float2*)(C + (size_t)(row + 8) * DIM + col) = o1;
        }
    }
}

__global__ __launch_bounds__(256, 1)
void gemm_mma(const float* __restrict__ A, const float* __restrict__ W,
              const float* __restrict__ bias, float* __restrict__ C) {
    extern __shared__ char sm[];
    gemm_body(A, W, bias, C, sm);
}

__global__ __launch_bounds__(256, 1)
void gemm_mma_qkv(const float* __restrict__ A,
                  const float* __restrict__ W0, const float* __restrict__ b0,
                  float* __restrict__ C0,
                  const float* __restrict__ W1, const float* __restrict__ b1,
                  float* __restrict__ C1,
                  const float* __restrict__ W2, const float* __restrict__ b2,
                  float* __restrict__ C2) {
    extern __shared__ char sm[];
    const float* W = (blockIdx.z == 0) ? W0 : (blockIdx.z == 1) ? W1 : W2;
    const float* b = (blockIdx.z == 0) ? b0 : (blockIdx.z == 1) ? b1 : b2;
    float* C = (blockIdx.z == 0) ? C0 : (blockIdx.z == 1) ? C1 : C2;
    gemm_body(A, W, b, C, sm);
}

// ===========================================================================
// Attention: FA2-style mma.sync bf16 split, ldmatrix fragment loads.
// Block: one (b,h) x 128 queries. 8 warps; warp owns 16 query rows.
// VTSTR = 272 B: multiple of 16 (ldmatrix alignment) and 68 words == 4 mod 32
// -> 8-lane groups cover all 32 banks, conflict-free.
// ===========================================================================
#define SQH 0
#define SQL 18432
#define SKH 36864
#define SKL 55296
#define SVH 73728
#define VTSTR 272
#define SVL (SVH + 64 * VTSTR)          // 91136
#define ATT_SMEM (SVL + 64 * VTSTR)     // 108544
#define QKSTR 144

__global__ __launch_bounds__(256, 1)
void attn_mma_kernel(const float* __restrict__ q, const float* __restrict__ k,
                     const float* __restrict__ v, float* __restrict__ ctx) {
    extern __shared__ char smc[];
    const int tid = threadIdx.x;
    const int wid = tid >> 5;
    const int lane = tid & 31;
    const int laneR = lane >> 2;
    const int laneC = lane & 3;
    const int b = blockIdx.x >> 4;
    const int h = blockIdx.x & 15;
    const int t0 = blockIdx.y * 128;
    const size_t base = (size_t)b * DIM + h * HD;
    const int mrow = wid * 16;

    const uint32_t smU = s2u(smc);
    const int g8 = lane >> 3;
    const int lr8 = lane & 7;
    const uint32_t qoff = (uint32_t)((mrow + (g8 & 1) * 8 + lr8) * QKSTR +
                                     (g8 >> 1) * 16);
    const uint32_t koff = (uint32_t)(lr8 * QKSTR + (g8 & 1) * 16);
    const uint32_t voff = (uint32_t)(lr8 * VTSTR + (g8 & 1) * 16);

    // ---- load Q tile (128x64), split into Qh/Ql ----
#pragma unroll
    for (int it = 0; it < 8; it++) {
        int task = tid + it * 256;
        int row = task >> 4;
        int c = (task & 15) << 2;
        float4 f = *(const float4*)(q + (size_t)(t0 + row) * ROWSTR + base + c);
        float l0, l1, l2, l3;
        uint2 uh, ul;
        uh.x = pack_hi(f.x, f.y, l0, l1);
        uh.y = pack_hi(f.z, f.w, l2, l3);
        ul.x = pack2(l0, l1);
        ul.y = pack2(l2, l3);
        *(uint2*)(smc + SQH + row * QKSTR + c * 2) = uh;
        *(uint2*)(smc + SQL + row * QKSTR + c * 2) = ul;
    }

    float oacc[8][4];
#pragma unroll
    for (int i = 0; i < 8; i++)
#pragma unroll
        for (int r = 0; r < 4; r++) oacc[i][r] = 0.f;
    float mr[2] = {-1e30f, -1e30f};
    float ls[2] = {0.f, 0.f};

    for (int kt = 0; kt < 8; kt++) {
        const int s0 = kt * 128;
        __syncthreads();

        // ---- K tile (128x64) split ----
#pragma unroll
        for (int it = 0; it < 8; it++) {
            int task = tid + it * 256;
            int row = task >> 4;
            int c = (task & 15) << 2;
            float4 f = *(const float4*)(k + (size_t)(s0 + row) * ROWSTR + base + c);
            float l0, l1, l2, l3;
            uint2 uh, ul;
            uh.x = pack_hi(f.x, f.y, l0, l1);
            uh.y = pack_hi(f.z, f.w, l2, l3);
            ul.x = pack2(l0, l1);
            ul.y = pack2(l2, l3);
            *(uint2*)(smc + SKH + row * QKSTR + c * 2) = uh;
            *(uint2*)(smc + SKL + row * QKSTR + c * 2) = ul;
        }

        // ---- V tile transposed: Vt[d][s], s-pairs packed in u32 ----
#pragma unroll
        for (int it = 0; it < 4; it++) {
            int task = tid + it * 256;
            int sp = task >> 4;
            int d0 = (task & 15) << 2;
            const float* vp = v + (size_t)(s0 + 2 * sp) * ROWSTR + base + d0;
            float4 f0 = *(const float4*)vp;
            float4 f1 = *(const float4*)(vp + ROWSTR);
            float a0[4] = {f0.x, f0.y, f0.z, f0.w};
            float a1[4] = {f1.x, f1.y, f1.z, f1.w};
#pragma unroll
            for (int e = 0; e < 4; e++) {
                float h0, h1;
                uint32_t uh = pack_hi(a0[e], a1[e], h0, h1);
                uint32_t ul = pack2(h0, h1);
                *(uint32_t*)(smc + SVH + (d0 + e) * VTSTR + sp * 4) = uh;
                *(uint32_t*)(smc + SVL + (d0 + e) * VTSTR + sp * 4) = ul;
            }
        }
        __syncthreads();

        // ---- S = Q K^T (16 rows x 128 keys), 3-pass split ----
        float sacc[16][4];
#pragma unroll
        for (int nt = 0; nt < 16; nt++)
#pragma unroll
            for (int r = 0; r < 4; r++) sacc[nt][r] = 0.f;

#pragma unroll
        for (int ks = 0; ks < 4; ks++) {
            uint32_t qa = smU + SQH + qoff + ks * 32;
            uint32_t ah[4], al[4];
            ldsm4(ah, qa);
            ldsm4(al, qa + (SQL - SQH));
#pragma unroll
            for (int nt = 0; nt < 16; nt++) {
                uint32_t ka = smU + SKH + koff + nt * (8 * QKSTR) + ks * 32;
                uint32_t bhf[2], blf[2];
                ldsm2(bhf, ka);
                ldsm2(blf, ka + (SKL - SKH));
                mma16816(sacc[nt], ah, bhf);
                mma16816(sacc[nt], ah, blf);
                mma16816(sacc[nt], al, bhf);
            }
        }

        // ---- online softmax ----
#pragma unroll
        for (int r = 0; r < 2; r++) {
            float mt = -1e30f;
#pragma unroll
            for (int nt = 0; nt < 16; nt++)
                mt = fmaxf(mt, fmaxf(sacc[nt][2 * r], sacc[nt][2 * r + 1]));
            mt = fmaxf(mt, __shfl_xor_sync(0xffffffffu, mt, 1));
            mt = fmaxf(mt, __shfl_xor_sync(0xffffffffu, mt, 2));
            float mnew = fmaxf(mr[r], mt);
            float corr = __expf((mr[r] - mnew) * 0.125f);
            mr[r] = mnew;
            const float mm = mnew * 0.125f;
            float rs = 0.f;
#pragma unroll
            for (int nt = 0; nt < 16; nt++) {
                float p0 = __expf(fmaf(sacc[nt][2 * r], 0.125f, -mm));
                float p1 = __expf(fmaf(sacc[nt][2 * r + 1], 0.125f, -mm));
                sacc[nt][2 * r] = p0;
                sacc[nt][2 * r + 1] = p1;
                rs += p0 + p1;
            }
            rs += __shfl_xor_sync(0xffffffffu, rs, 1);
            rs += __shfl_xor_sync(0xffffffffu, rs, 2);
            ls[r] = ls[r] * corr + rs;
#pragma unroll
            for (int nt2 = 0; nt2 < 8; nt2++) {
                oacc[nt2][2 * r] *= corr;
                oacc[nt2][2 * r + 1] *= corr;
            }
        }

        // ---- O += P @ V (P split in registers, V frags via ldmatrix) ----
#pragma unroll
        for (int j = 0; j < 8; j++) {
            uint32_t ph[4], pl[4];
            float l0, l1;
            ph[0] = pack_hi(sacc[2 * j][0], sacc[2 * j][1], l0, l1);
            pl[0] = pack2(l0, l1);
            ph[1] = pack_hi(sacc[2 * j][2], sacc[2 * j][3], l0, l1);
            pl[1] = pack2(l0, l1);
            ph[2] = pack_hi(sacc[2 * j + 1][0], sacc[2 * j + 1][1], l0, l1);
            pl[2] = pack2(l0, l1);
            ph[3] = pack_hi(sacc[2 * j + 1][2], sacc[2 * j + 1][3], l0, l1);
            pl[3] = pack2(l0, l1);
#pragma unroll
            for (int nt2 = 0; nt2 < 8; nt2++) {
                uint32_t va = smU + SVH + voff + nt2 * (8 * VTSTR) + j * 32;
                uint32_t vhf[2], vlf[2];
                ldsm2(vhf, va);
                ldsm2(vlf, va + (SVL - SVH));
                mma16816(oacc[nt2], ph, vhf);
                mma16816(oacc[nt2], ph, vlf);
                mma16816(oacc[nt2], pl, vhf);
            }
        }
    }

    // ---- normalize and store ----
    const float inv0 = 1.f / ls[0];
    const float inv1 = 1.f / ls[1];
    const int r0 = t0 + mrow + laneR;
#pragma unroll
    for (int nt2 = 0; nt2 < 8; nt2++) {
        const size_t col = base + nt2 * 8 + laneC * 2;
        *(float2*)(ctx + (size_t)r0 * ROWSTR + col) =
            make_float2(oacc[nt2][0] * inv0, oacc[nt2][1] * inv0);
        *(float2*)(ctx + (size_t)(r0 + 8) * ROWSTR + col) =
            make_float2(oacc[nt2][2] * inv1, oacc[nt2][3] * inv1);
    }
}

// ===========================================================================
// Fused residual-add + LayerNorm over rows of 1024. One block per row.
// ===========================================================================
__global__ __launch_bounds__(256)
void add_ln_kernel(const float* __restrict__ a, const float* __restrict__ res,
                   const float* __restrict__ gma, const float* __restrict__ bta,
                   float* __restrict__ out) {
    __shared__ float red[16];
    const int row = blockIdx.x;
    const int tid = threadIdx.x;

    float4 va = *(const float4*)(a + (size_t)row * DIM + tid * 4);
    float4 vr = *(const float4*)(res + (size_t)row * DIM + tid * 4);
    float4 x;
    x.x = va.x + vr.x; x.y = va.y + vr.y; x.z = va.z + vr.z; x.w = va.w + vr.w;

    float sum = x.x + x.y + x.z + x.w;
    float sq = x.x * x.x + x.y * x.y + x.z * x.z + x.w * x.w;
#pragma unroll
    for (int d = 16; d; d >>= 1) {
        sum += __shfl_xor_sync(0xffffffffu, sum, d);
        sq += __shfl_xor_sync(0xffffffffu, sq, d);
    }
    const int warp = tid >> 5;
    if ((tid & 31) == 0) { red[warp] = sum; red[8 + warp] = sq; }
    __syncthreads();
    if (tid < 32) {
        float s = (tid < 8) ? red[tid] : 0.f;
        float q2 = (tid < 8) ? red[8 + tid] : 0.f;
#pragma unroll
        for (int d = 4; d; d >>= 1) {
            s += __shfl_xor_sync(0xffffffffu, s, d);
            q2 += __shfl_xor_sync(0xffffffffu, q2, d);
        }
        if (tid == 0) { red[0] = s; red[1] = q2; }
    }
    __syncthreads();
    const float mean = red[0] * (1.f / DIM);
    const float var = red[1] * (1.f / DIM) - mean * mean;
    const float rstd = rsqrtf(var + 1e-5f);

    float4 g4 = *(const float4*)(gma + tid * 4);
    float4 b4 = *(const float4*)(bta + tid * 4);
    float4 o;
    o.x = (x.x - mean) * rstd * g4.x + b4.x;
    o.y = (x.y - mean) * rstd * g4.y + b4.y;
    o.z = (x.z - mean) * rstd * g4.z + b4.z;
    o.w = (x.w - mean) * rstd * g4.w + b4.w;
    *(float4*)(out + (size_t)row * DIM + tid * 4) = o;
}

// ===========================================================================
// launch
// ===========================================================================
extern "C" void kernel_launch(void* const* d_in, const int* in_sizes, int n_in,
                              void* d_out, int out_size) {
    const float* x  = (const float*)d_in[0];
    const float* Wq = (const float*)d_in[1];
    const float* bq = (const float*)d_in[2];
    const float* Wk = (const float*)d_in[3];
    const float* bk = (const float*)d_in[4];
    const float* Wv = (const float*)d_in[5];
    const float* bv = (const float*)d_in[6];
    const float* Wo = (const float*)d_in[7];
    const float* bo = (const float*)d_in[8];
    const float* Wl = (const float*)d_in[9];
    const float* bl = (const float*)d_in[10];
    const float* g1 = (const float*)d_in[11];
    const float* b1 = (const float*)d_in[12];
    const float* g2 = (const float*)d_in[13];
    const float* b2 = (const float*)d_in[14];
    float* out = (float*)d_out;

    float *q, *k, *v, *ctx, *t1, *hh, *t2;
    cudaGetSymbolAddress((void**)&q, g_q);
    cudaGetSymbolAddress((void**)&k, g_k);
    cudaGetSymbolAddress((void**)&v, g_v);
    cudaGetSymbolAddress((void**)&ctx, g_ctx);
    cudaGetSymbolAddress((void**)&t1, g_t1);
    cudaGetSymbolAddress((void**)&hh, g_h);
    cudaGetSymbolAddress((void**)&t2, g_t2);

    cudaFuncSetAttribute(attn_mma_kernel,
                         cudaFuncAttributeMaxDynamicSharedMemorySize, ATT_SMEM);
    cudaFuncSetAttribute(gemm_mma,
                         cudaFuncAttributeMaxDynamicSharedMemorySize, GEMM_SMEM);
    cudaFuncSetAttribute(gemm_mma_qkv,
                         cudaFuncAttributeMaxDynamicSharedMemorySize, GEMM_SMEM);

    dim3 ggrid(DIM / 128, NTOK / 128);      // (8, 32)
    dim3 ggrid3(DIM / 128, NTOK / 128, 3);  // QKV batched
    dim3 gblk(256);

    gemm_mma_qkv<<<ggrid3, gblk, GEMM_SMEM>>>(x, Wq, bq, q, Wk, bk, k, Wv, bv, v);
    attn_mma_kernel<<<dim3(BB * NH, TT / 128), 256, ATT_SMEM>>>(q, k, v, ctx);
    gemm_mma<<<ggrid, gblk, GEMM_SMEM>>>(ctx, Wo, bo, t1);
    add_ln_kernel<<<NTOK, 256>>>(t1, x, g1, b1, hh);
    gemm_mma<<<ggrid, gblk, GEMM_SMEM>>>(hh, Wl, bl, t2);
    add_ln_kernel<<<NTOK, 256>>>(t2, hh, g2, b2, out);
}

// round 15
// speedup vs baseline: 1.4936x; 1.3999x over previous
#include <cuda_runtime.h>
#include <cuda_fp16.h>
#include <cstdint>

#define TT 1024
#define BB 4
#define DIM 1024
#define NH 16
#define HD 64
#define NTOK (TT * BB)     // 4096 tokens
#define ROWSTR (BB * DIM)  // 4096 floats per t-step

// ---------------- scratch (device globals; no allocations allowed) --------
__device__ float g_q[NTOK * DIM];
__device__ float g_k[NTOK * DIM];
__device__ float g_v[NTOK * DIM];
__device__ float g_ctx[NTOK * DIM];
__device__ float g_t1[NTOK * DIM];
__device__ float g_h[NTOK * DIM];
__device__ float g_t2[NTOK * DIM];

// ===========================================================================
// helpers (fp16 two-term split: x = hi + lo, |lo| <= 2^-11 |x|)
// ===========================================================================
__device__ __forceinline__ void mma16816(float* c, const uint32_t* a,
                                         const uint32_t* b) {
    asm volatile(
        "mma.sync.aligned.m16n8k16.row.col.f32.f16.f16.f32 "
        "{%0,%1,%2,%3}, {%4,%5,%6,%7}, {%8,%9}, {%0,%1,%2,%3};"
        : "+f"(c[0]), "+f"(c[1]), "+f"(c[2]), "+f"(c[3])
        : "r"(a[0]), "r"(a[1]), "r"(a[2]), "r"(a[3]), "r"(b[0]), "r"(b[1]));
}

__device__ __forceinline__ uint32_t pack_hi(float v0, float v1, float& l0,
                                            float& l1) {
    __half h0 = __float2half_rn(v0);
    __half h1 = __float2half_rn(v1);
    l0 = v0 - __half2float(h0);
    l1 = v1 - __half2float(h1);
    __half2 p;
    p.x = h0; p.y = h1;
    return *(uint32_t*)&p;
}

__device__ __forceinline__ uint32_t pack2(float v0, float v1) {
    __half2 p = __floats2half2_rn(v0, v1);
    return *(uint32_t*)&p;
}

// ===========================================================================
// GEMM via mma.sync fp16 2-pass split: C = (Ah + Al) @ Bh^T  (B lo dropped,
// error ~2^-12 rms). 128x128 tile, BK=32, 8 warps, double buffer, occ 2.
// smem per stage: Ah, Al, Bh tiles of 128x32 fp16 padded to 80B rows.
// ===========================================================================
#define TILEB (128 * 80)
#define STAGEB (3 * TILEB)
#define GEMM_SMEM (2 * STAGEB)   // 61440 B -> 2 CTAs/SM

__device__ __forceinline__ void gemm_body(const float* __restrict__ A,
                                          const float* __restrict__ W,
                                          const float* __restrict__ bias,
                                          float* __restrict__ C, char* sm) {
    const int tid = threadIdx.x;
    const int wid = tid >> 5;
    const int lane = tid & 31;
    const int laneR = lane >> 2;
    const int laneC = lane & 3;
    const int mBase = (wid >> 2) * 64;
    const int nBase = (wid & 3) * 32;
    const int m0 = blockIdx.y * 128;
    const int n0 = blockIdx.x * 128;

    const int lrow = tid >> 3;
    const int lc4 = (tid & 7) << 2;

    float acc[4][4][4];
#pragma unroll
    for (int i = 0; i < 4; i++)
#pragma unroll
        for (int j = 0; j < 4; j++)
#pragma unroll
            for (int r = 0; r < 4; r++) acc[i][j][r] = 0.f;

    float4 ra[4], rb[4];

    auto load_g = [&](int ch) {
        const int k0 = ch * 32;
#pragma unroll
        for (int it = 0; it < 4; it++) {
            int row = lrow + it * 32;
            ra[it] = *(const float4*)(A + (size_t)(m0 + row) * DIM + k0 + lc4);
            rb[it] = *(const float4*)(W + (size_t)(n0 + row) * DIM + k0 + lc4);
        }
    };

    auto cvt_store = [&](int b) {
        char* st = sm + b * STAGEB;
#pragma unroll
        for (int it = 0; it < 4; it++) {
            int row = lrow + it * 32;
            uint32_t bo = row * 80 + lc4 * 2;
            float l0, l1, l2, l3;
            uint2 uh, ul;
            uh.x = pack_hi(ra[it].x, ra[it].y, l0, l1);
            uh.y = pack_hi(ra[it].z, ra[it].w, l2, l3);
            ul.x = pack2(l0, l1);
            ul.y = pack2(l2, l3);
            *(uint2*)(st + bo) = uh;                    // Ah
            *(uint2*)(st + TILEB + bo) = ul;            // Al
            uint2 wh;
            wh.x = pack2(rb[it].x, rb[it].y);
            wh.y = pack2(rb[it].z, rb[it].w);
            *(uint2*)(st + 2 * TILEB + bo) = wh;        // Bh only
        }
    };

    auto mma_stage = [&](int b) {
        const char* sb = sm + b * STAGEB;
#pragma unroll
        for (int s = 0; s < 2; s++) {
            const uint32_t so = s * 32 + laneC * 4;
            uint32_t bh[4][2];
#pragma unroll
            for (int tj = 0; tj < 4; tj++) {
                uint32_t r = (nBase + tj * 8 + laneR) * 80 + so;
                bh[tj][0] = *(const uint32_t*)(sb + 2 * TILEB + r);
                bh[tj][1] = *(const uint32_t*)(sb + 2 * TILEB + r + 16);
            }
#pragma unroll
            for (int ti = 0; ti < 4; ti++) {
                uint32_t r = (mBase + ti * 16 + laneR) * 80 + so;
                uint32_t ah[4], al[4];
                ah[0] = *(const uint32_t*)(sb + r);
                ah[1] = *(const uint32_t*)(sb + r + 640);
                ah[2] = *(const uint32_t*)(sb + r + 16);
                ah[3] = *(const uint32_t*)(sb + r + 656);
                al[0] = *(const uint32_t*)(sb + TILEB + r);
                al[1] = *(const uint32_t*)(sb + TILEB + r + 640);
                al[2] = *(const uint32_t*)(sb + TILEB + r + 16);
                al[3] = *(const uint32_t*)(sb + TILEB + r + 656);
#pragma unroll
                for (int tj = 0; tj < 4; tj++) {
                    mma16816(acc[ti][tj], ah, bh[tj]);
                    mma16816(acc[ti][tj], al, bh[tj]);
                }
            }
        }
    };

    load_g(0);
    cvt_store(0);
    __syncthreads();

    for (int ch = 0; ch < 32; ch++) {
        const int b = ch & 1;
        if (ch < 31) load_g(ch + 1);
        mma_stage(b);
        if (ch < 31) cvt_store(b ^ 1);
        __syncthreads();
    }

#pragma unroll
    for (int ti = 0; ti < 4; ti++) {
        const int row = m0 + mBase + ti * 16 + laneR;
#pragma unroll
        for (int tj = 0; tj < 4; tj++) {
            const int col = n0 + nBase + tj * 8 + laneC * 2;
            const float b0 = __ldg(bias + col);
            const float b1 = __ldg(bias + col + 1);
            float2 o0 = make_float2(acc[ti][tj][0] + b0, acc[ti][tj][1] + b1);
            float2 o1 = make_float2(acc[ti][tj][2] + b0, acc[ti][tj][3] + b1);
            *(float2*)(C + (size_t)row * DIM + col) = o0;
            *(float2*)(C + (size_t)(row + 8) * DIM + col) = o1;
        }
    }
}

__global__ __launch_bounds__(256, 2)
void gemm_mma(const float* __restrict__ A, const float* __restrict__ W,
              const float* __restrict__ bias, float* __restrict__ C) {
    extern __shared__ char sm[];
    gemm_body(A, W, bias, C, sm);
}

__global__ __launch_bounds__(256, 2)
void gemm_mma_qkv(const float* __restrict__ A,
                  const float* __restrict__ W0, const float* __restrict__ b0,
                  float* __restrict__ C0,
                  const float* __restrict__ W1, const float* __restrict__ b1,
                  float* __restrict__ C1,
                  const float* __restrict__ W2, const float* __restrict__ b2,
                  float* __restrict__ C2) {
    extern __shared__ char sm[];
    const float* W = (blockIdx.z == 0) ? W0 : (blockIdx.z == 1) ? W1 : W2;
    const float* b = (blockIdx.z == 0) ? b0 : (blockIdx.z == 1) ? b1 : b2;
    float* C = (blockIdx.z == 0) ? C0 : (blockIdx.z == 1) ? C1 : C2;
    gemm_body(A, W, b, C, sm);
}

// ===========================================================================
// Attention: FA2-style mma.sync fp16 2-pass split.
// S = (Qh+Ql) K_h^T  (K lo dropped);  O += (Ph+Pl) Vt_h  (V lo dropped).
// Block: one (b,h) x 128 queries, 8 warps, 16 query rows/warp.
// smem: Qh/Ql/Kh [128][144B rows], Vth [64][272B rows]  -> 72704 B.
// ===========================================================================
#define SQH 0
#define SQL 18432
#define SKH 36864
#define SVH 55296
#define VTSTR 272
#define ATT_SMEM (SVH + 64 * VTSTR)   // 72704
#define QKSTR 144

__global__ __launch_bounds__(256, 1)
void attn_mma_kernel(const float* __restrict__ q, const float* __restrict__ k,
                     const float* __restrict__ v, float* __restrict__ ctx) {
    extern __shared__ char smc[];
    const int tid = threadIdx.x;
    const int wid = tid >> 5;
    const int lane = tid & 31;
    const int laneR = lane >> 2;
    const int laneC = lane & 3;
    const int b = blockIdx.x >> 4;
    const int h = blockIdx.x & 15;
    const int t0 = blockIdx.y * 128;
    const size_t base = (size_t)b * DIM + h * HD;
    const int mrow = wid * 16;

    // ---- load Q tile (128x64), split into Qh/Ql ----
#pragma unroll
    for (int it = 0; it < 8; it++) {
        int task = tid + it * 256;
        int row = task >> 4;
        int c = (task & 15) << 2;
        float4 f = *(const float4*)(q + (size_t)(t0 + row) * ROWSTR + base + c);
        float l0, l1, l2, l3;
        uint2 uh, ul;
        uh.x = pack_hi(f.x, f.y, l0, l1);
        uh.y = pack_hi(f.z, f.w, l2, l3);
        ul.x = pack2(l0, l1);
        ul.y = pack2(l2, l3);
        *(uint2*)(smc + SQH + row * QKSTR + c * 2) = uh;
        *(uint2*)(smc + SQL + row * QKSTR + c * 2) = ul;
    }

    float oacc[8][4];
#pragma unroll
    for (int i = 0; i < 8; i++)
#pragma unroll
        for (int r = 0; r < 4; r++) oacc[i][r] = 0.f;
    float mr[2] = {-1e30f, -1e30f};
    float ls[2] = {0.f, 0.f};

    for (int kt = 0; kt < 8; kt++) {
        const int s0 = kt * 128;
        __syncthreads();

        // ---- K tile (128x64), hi only ----
#pragma unroll
        for (int it = 0; it < 8; it++) {
            int task = tid + it * 256;
            int row = task >> 4;
            int c = (task & 15) << 2;
            float4 f = *(const float4*)(k + (size_t)(s0 + row) * ROWSTR + base + c);
            uint2 uh;
            uh.x = pack2(f.x, f.y);
            uh.y = pack2(f.z, f.w);
            *(uint2*)(smc + SKH + row * QKSTR + c * 2) = uh;
        }

        // ---- V tile transposed (hi only): Vt[d][s], s-pairs in u32 ----
#pragma unroll
        for (int it = 0; it < 4; it++) {
            int task = tid + it * 256;
            int sp = task >> 4;
            int d0 = (task & 15) << 2;
            const float* vp = v + (size_t)(s0 + 2 * sp) * ROWSTR + base + d0;
            float4 f0 = *(const float4*)vp;
            float4 f1 = *(const float4*)(vp + ROWSTR);
            float a0[4] = {f0.x, f0.y, f0.z, f0.w};
            float a1[4] = {f1.x, f1.y, f1.z, f1.w};
#pragma unroll
            for (int e = 0; e < 4; e++) {
                *(uint32_t*)(smc + SVH + (d0 + e) * VTSTR + sp * 4) =
                    pack2(a0[e], a1[e]);
            }
        }
        __syncthreads();

        // ---- S = Q K^T (16 rows x 128 keys), 2-pass split on Q ----
        float sacc[16][4];
#pragma unroll
        for (int nt = 0; nt < 16; nt++)
#pragma unroll
            for (int r = 0; r < 4; r++) sacc[nt][r] = 0.f;

#pragma unroll
        for (int ks = 0; ks < 4; ks++) {
            const uint32_t qb = (mrow + laneR) * QKSTR + ks * 32 + laneC * 4;
            uint32_t ah[4], al[4];
            ah[0] = *(const uint32_t*)(smc + SQH + qb);
            ah[1] = *(const uint32_t*)(smc + SQH + qb + 8 * QKSTR);
            ah[2] = *(const uint32_t*)(smc + SQH + qb + 16);
            ah[3] = *(const uint32_t*)(smc + SQH + qb + 8 * QKSTR + 16);
            al[0] = *(const uint32_t*)(smc + SQL + qb);
            al[1] = *(const uint32_t*)(smc + SQL + qb + 8 * QKSTR);
            al[2] = *(const uint32_t*)(smc + SQL + qb + 16);
            al[3] = *(const uint32_t*)(smc + SQL + qb + 8 * QKSTR + 16);
#pragma unroll
            for (int nt = 0; nt < 16; nt++) {
                const uint32_t kb =
                    (nt * 8 + laneR) * QKSTR + ks * 32 + laneC * 4;
                uint32_t bhf[2];
                bhf[0] = *(const uint32_t*)(smc + SKH + kb);
                bhf[1] = *(const uint32_t*)(smc + SKH + kb + 16);
                mma16816(sacc[nt], ah, bhf);
                mma16816(sacc[nt], al, bhf);
            }
        }

        // ---- online softmax ----
#pragma unroll
        for (int r = 0; r < 2; r++) {
            float mt = -1e30f;
#pragma unroll
            for (int nt = 0; nt < 16; nt++)
                mt = fmaxf(mt, fmaxf(sacc[nt][2 * r], sacc[nt][2 * r + 1]));
            mt = fmaxf(mt, __shfl_xor_sync(0xffffffffu, mt, 1));
            mt = fmaxf(mt, __shfl_xor_sync(0xffffffffu, mt, 2));
            float mnew = fmaxf(mr[r], mt);
            float corr = __expf((mr[r] - mnew) * 0.125f);
            mr[r] = mnew;
            const float mm = mnew * 0.125f;
            float rs = 0.f;
#pragma unroll
            for (int nt = 0; nt < 16; nt++) {
                float p0 = __expf(fmaf(sacc[nt][2 * r], 0.125f, -mm));
                float p1 = __expf(fmaf(sacc[nt][2 * r + 1], 0.125f, -mm));
                sacc[nt][2 * r] = p0;
                sacc[nt][2 * r + 1] = p1;
                rs += p0 + p1;
            }
            rs += __shfl_xor_sync(0xffffffffu, rs, 1);
            rs += __shfl_xor_sync(0xffffffffu, rs, 2);
            ls[r] = ls[r] * corr + rs;
#pragma unroll
            for (int nt2 = 0; nt2 < 8; nt2++) {
                oacc[nt2][2 * r] *= corr;
                oacc[nt2][2 * r + 1] *= corr;
            }
        }

        // ---- O += P @ V (P split in registers, V hi only) ----
#pragma unroll
        for (int j = 0; j < 8; j++) {
            uint32_t ph[4], pl[4];
            float l0, l1;
            ph[0] = pack_hi(sacc[2 * j][0], sacc[2 * j][1], l0, l1);
            pl[0] = pack2(l0, l1);
            ph[1] = pack_hi(sacc[2 * j][2], sacc[2 * j][3], l0, l1);
            pl[1] = pack2(l0, l1);
            ph[2] = pack_hi(sacc[2 * j + 1][0], sacc[2 * j + 1][1], l0, l1);
            pl[2] = pack2(l0, l1);
            ph[3] = pack_hi(sacc[2 * j + 1][2], sacc[2 * j + 1][3], l0, l1);
            pl[3] = pack2(l0, l1);
#pragma unroll
            for (int nt2 = 0; nt2 < 8; nt2++) {
                const uint32_t vb =
                    (nt2 * 8 + laneR) * VTSTR + j * 32 + laneC * 4;
                uint32_t vhf[2];
                vhf[0] = *(const uint32_t*)(smc + SVH + vb);
                vhf[1] = *(const uint32_t*)(smc + SVH + vb + 16);
                mma16816(oacc[nt2], ph, vhf);
                mma16816(oacc[nt2], pl, vhf);
            }
        }
    }

    // ---- normalize and store ----
    const float inv0 = 1.f / ls[0];
    const float inv1 = 1.f / ls[1];
    const int r0 = t0 + mrow + laneR;
#pragma unroll
    for (int nt2 = 0; nt2 < 8; nt2++) {
        const size_t col = base + nt2 * 8 + laneC * 2;
        *(float2*)(ctx + (size_t)r0 * ROWSTR + col) =
            make_float2(oacc[nt2][0] * inv0, oacc[nt2][1] * inv0);
        *(float2*)(ctx + (size_t)(r0 + 8) * ROWSTR + col) =
            make_float2(oacc[nt2][2] * inv1, oacc[nt2][3] * inv1);
    }
}

// ===========================================================================
// Fused residual-add + LayerNorm over rows of 1024. One block per row.
// ===========================================================================
__global__ __launch_bounds__(256)
void add_ln_kernel(const float* __restrict__ a, const float* __restrict__ res,
                   const float* __restrict__ gma, const float* __restrict__ bta,
                   float* __restrict__ out) {
    __shared__ float red[16];
    const int row = blockIdx.x;
    const int tid = threadIdx.x;

    float4 va = *(const float4*)(a + (size_t)row * DIM + tid * 4);
    float4 vr = *(const float4*)(res + (size_t)row * DIM + tid * 4);
    float4 x;
    x.x = va.x + vr.x; x.y = va.y + vr.y; x.z = va.z + vr.z; x.w = va.w + vr.w;

    float sum = x.x + x.y + x.z + x.w;
    float sq = x.x * x.x + x.y * x.y + x.z * x.z + x.w * x.w;
#pragma unroll
    for (int d = 16; d; d >>= 1) {
        sum += __shfl_xor_sync(0xffffffffu, sum, d);
        sq += __shfl_xor_sync(0xffffffffu, sq, d);
    }
    const int warp = tid >> 5;
    if ((tid & 31) == 0) { red[warp] = sum; red[8 + warp] = sq; }
    __syncthreads();
    if (tid < 32) {
        float s = (tid < 8) ? red[tid] : 0.f;
        float q2 = (tid < 8) ? red[8 + tid] : 0.f;
#pragma unroll
        for (int d = 4; d; d >>= 1) {
            s += __shfl_xor_sync(0xffffffffu, s, d);
            q2 += __shfl_xor_sync(0xffffffffu, q2, d);
        }
        if (tid == 0) { red[0] = s; red[1] = q2; }
    }
    __syncthreads();
    const float mean = red[0] * (1.f / DIM);
    const float var = red[1] * (1.f / DIM) - mean * mean;
    const float rstd = rsqrtf(var + 1e-5f);

    float4 g4 = *(const float4*)(gma + tid * 4);
    float4 b4 = *(const float4*)(bta + tid * 4);
    float4 o;
    o.x = (x.x - mean) * rstd * g4.x + b4.x;
    o.y = (x.y - mean) * rstd * g4.y + b4.y;
    o.z = (x.z - mean) * rstd * g4.z + b4.z;
    o.w = (x.w - mean) * rstd * g4.w + b4.w;
    *(float4*)(out + (size_t)row * DIM + tid * 4) = o;
}

// ===========================================================================
// launch
// ===========================================================================
extern "C" void kernel_launch(void* const* d_in, const int* in_sizes, int n_in,
                              void* d_out, int out_size) {
    const float* x  = (const float*)d_in[0];
    const float* Wq = (const float*)d_in[1];
    const float* bq = (const float*)d_in[2];
    const float* Wk = (const float*)d_in[3];
    const float* bk = (const float*)d_in[4];
    const float* Wv = (const float*)d_in[5];
    const float* bv = (const float*)d_in[6];
    const float* Wo = (const float*)d_in[7];
    const float* bo = (const float*)d_in[8];
    const float* Wl = (const float*)d_in[9];
    const float* bl = (const float*)d_in[10];
    const float* g1 = (const float*)d_in[11];
    const float* b1 = (const float*)d_in[12];
    const float* g2 = (const float*)d_in[13];
    const float* b2 = (const float*)d_in[14];
    float* out = (float*)d_out;

    float *q, *k, *v, *ctx, *t1, *hh, *t2;
    cudaGetSymbolAddress((void**)&q, g_q);
    cudaGetSymbolAddress((void**)&k, g_k);
    cudaGetSymbolAddress((void**)&v, g_v);
    cudaGetSymbolAddress((void**)&ctx, g_ctx);
    cudaGetSymbolAddress((void**)&t1, g_t1);
    cudaGetSymbolAddress((void**)&hh, g_h);
    cudaGetSymbolAddress((void**)&t2, g_t2);

    cudaFuncSetAttribute(attn_mma_kernel,
                         cudaFuncAttributeMaxDynamicSharedMemorySize, ATT_SMEM);
    cudaFuncSetAttribute(gemm_mma,
                         cudaFuncAttributeMaxDynamicSharedMemorySize, GEMM_SMEM);
    cudaFuncSetAttribute(gemm_mma_qkv,
                         cudaFuncAttributeMaxDynamicSharedMemorySize, GEMM_SMEM);

    dim3 ggrid(DIM / 128, NTOK / 128);      // (8, 32)
    dim3 ggrid3(DIM / 128, NTOK / 128, 3);  // QKV batched
    dim3 gblk(256);

    gemm_mma_qkv<<<ggrid3, gblk, GEMM_SMEM>>>(x, Wq, bq, q, Wk, bk, k, Wv, bv, v);
    attn_mma_kernel<<<dim3(BB * NH, TT / 128), 256, ATT_SMEM>>>(q, k, v, ctx);
    gemm_mma<<<ggrid, gblk, GEMM_SMEM>>>(ctx, Wo, bo, t1);
    add_ln_kernel<<<NTOK, 256>>>(t1, x, g1, b1, hh);
    gemm_mma<<<ggrid, gblk, GEMM_SMEM>>>(hh, Wl, bl, t2);
    add_ln_kernel<<<NTOK, 256>>>(t2, hh, g2, b2, out);
}

// round 16
// speedup vs baseline: 1.5930x; 1.0666x over previous
#include <cuda_runtime.h>
#include <cuda_fp16.h>
#include <cstdint>

#define TT 1024
#define BB 4
#define DIM 1024
#define NH 16
#define HD 64
#define NTOK (TT * BB)     // 4096 tokens
#define ROWSTR (BB * DIM)  // 4096 floats per t-step

// ---------------- scratch (device globals; no allocations allowed) --------
__device__ float g_q[NTOK * DIM];
__device__ float g_k[NTOK * DIM];
__device__ float g_v[NTOK * DIM];
__device__ float g_ctx[NTOK * DIM];
__device__ float g_t1[NTOK * DIM];
__device__ float g_h[NTOK * DIM];
__device__ float g_t2[NTOK * DIM];

// ===========================================================================
// helpers (fp16 two-term split: x = hi + lo, |lo| <= 2^-11 |x|)
// ===========================================================================
__device__ __forceinline__ void mma16816(float* c, const uint32_t* a,
                                         const uint32_t* b) {
    asm volatile(
        "mma.sync.aligned.m16n8k16.row.col.f32.f16.f16.f32 "
        "{%0,%1,%2,%3}, {%4,%5,%6,%7}, {%8,%9}, {%0,%1,%2,%3};"
        : "+f"(c[0]), "+f"(c[1]), "+f"(c[2]), "+f"(c[3])
        : "r"(a[0]), "r"(a[1]), "r"(a[2]), "r"(a[3]), "r"(b[0]), "r"(b[1]));
}

__device__ __forceinline__ uint32_t pack_hi(float v0, float v1, float& l0,
                                            float& l1) {
    __half h0 = __float2half_rn(v0);
    __half h1 = __float2half_rn(v1);
    l0 = v0 - __half2float(h0);
    l1 = v1 - __half2float(h1);
    __half2 p;
    p.x = h0; p.y = h1;
    return *(uint32_t*)&p;
}

__device__ __forceinline__ uint32_t pack2(float v0, float v1) {
    __half2 p = __floats2half2_rn(v0, v1);
    return *(uint32_t*)&p;
}

// ===========================================================================
// GEMM via mma.sync fp16 2-pass split: C = (Ah + Al) @ Bh^T  (B lo dropped).
// 128x128 tile, BK=32, 8 warps, double buffer, occ 2.
// ===========================================================================
#define TILEB (128 * 80)
#define STAGEB (3 * TILEB)
#define GEMM_SMEM (2 * STAGEB)   // 61440 B -> 2 CTAs/SM

__device__ __forceinline__ void gemm_body(const float* __restrict__ A,
                                          const float* __restrict__ W,
                                          const float* __restrict__ bias,
                                          float* __restrict__ C, char* sm) {
    const int tid = threadIdx.x;
    const int wid = tid >> 5;
    const int lane = tid & 31;
    const int laneR = lane >> 2;
    const int laneC = lane & 3;
    const int mBase = (wid >> 2) * 64;
    const int nBase = (wid & 3) * 32;
    const int m0 = blockIdx.y * 128;
    const int n0 = blockIdx.x * 128;

    const int lrow = tid >> 3;
    const int lc4 = (tid & 7) << 2;

    float acc[4][4][4];
#pragma unroll
    for (int i = 0; i < 4; i++)
#pragma unroll
        for (int j = 0; j < 4; j++)
#pragma unroll
            for (int r = 0; r < 4; r++) acc[i][j][r] = 0.f;

    float4 ra[4], rb[4];

    auto load_g = [&](int ch) {
        const int k0 = ch * 32;
#pragma unroll
        for (int it = 0; it < 4; it++) {
            int row = lrow + it * 32;
            ra[it] = *(const float4*)(A + (size_t)(m0 + row) * DIM + k0 + lc4);
            rb[it] = *(const float4*)(W + (size_t)(n0 + row) * DIM + k0 + lc4);
        }
    };

    auto cvt_store = [&](int b) {
        char* st = sm + b * STAGEB;
#pragma unroll
        for (int it = 0; it < 4; it++) {
            int row = lrow + it * 32;
            uint32_t bo = row * 80 + lc4 * 2;
            float l0, l1, l2, l3;
            uint2 uh, ul;
            uh.x = pack_hi(ra[it].x, ra[it].y, l0, l1);
            uh.y = pack_hi(ra[it].z, ra[it].w, l2, l3);
            ul.x = pack2(l0, l1);
            ul.y = pack2(l2, l3);
            *(uint2*)(st + bo) = uh;                    // Ah
            *(uint2*)(st + TILEB + bo) = ul;            // Al
            uint2 wh;
            wh.x = pack2(rb[it].x, rb[it].y);
            wh.y = pack2(rb[it].z, rb[it].w);
            *(uint2*)(st + 2 * TILEB + bo) = wh;        // Bh only
        }
    };

    auto mma_stage = [&](int b) {
        const char* sb = sm + b * STAGEB;
#pragma unroll
        for (int s = 0; s < 2; s++) {
            const uint32_t so = s * 32 + laneC * 4;
            uint32_t bh[4][2];
#pragma unroll
            for (int tj = 0; tj < 4; tj++) {
                uint32_t r = (nBase + tj * 8 + laneR) * 80 + so;
                bh[tj][0] = *(const uint32_t*)(sb + 2 * TILEB + r);
                bh[tj][1] = *(const uint32_t*)(sb + 2 * TILEB + r + 16);
            }
#pragma unroll
            for (int ti = 0; ti < 4; ti++) {
                uint32_t r = (mBase + ti * 16 + laneR) * 80 + so;
                uint32_t ah[4], al[4];
                ah[0] = *(const uint32_t*)(sb + r);
                ah[1] = *(const uint32_t*)(sb + r + 640);
                ah[2] = *(const uint32_t*)(sb + r + 16);
                ah[3] = *(const uint32_t*)(sb + r + 656);
                al[0] = *(const uint32_t*)(sb + TILEB + r);
                al[1] = *(const uint32_t*)(sb + TILEB + r + 640);
                al[2] = *(const uint32_t*)(sb + TILEB + r + 16);
                al[3] = *(const uint32_t*)(sb + TILEB + r + 656);
#pragma unroll
                for (int tj = 0; tj < 4; tj++) {
                    mma16816(acc[ti][tj], ah, bh[tj]);
                    mma16816(acc[ti][tj], al, bh[tj]);
                }
            }
        }
    };

    load_g(0);
    cvt_store(0);
    __syncthreads();

    for (int ch = 0; ch < 32; ch++) {
        const int b = ch & 1;
        if (ch < 31) load_g(ch + 1);
        mma_stage(b);
        if (ch < 31) cvt_store(b ^ 1);
        __syncthreads();
    }

#pragma unroll
    for (int ti = 0; ti < 4; ti++) {
        const int row = m0 + mBase + ti * 16 + laneR;
#pragma unroll
        for (int tj = 0; tj < 4; tj++) {
            const int col = n0 + nBase + tj * 8 + laneC * 2;
            const float b0 = __ldg(bias + col);
            const float b1 = __ldg(bias + col + 1);
            float2 o0 = make_float2(acc[ti][tj][0] + b0, acc[ti][tj][1] + b1);
            float2 o1 = make_float2(acc[ti][tj][2] + b0, acc[ti][tj][3] + b1);
            *(float2*)(C + (size_t)row * DIM + col) = o0;
            *(float2*)(C + (size_t)(row + 8) * DIM + col) = o1;
        }
    }
}

__global__ __launch_bounds__(256, 2)
void gemm_mma(const float* __restrict__ A, const float* __restrict__ W,
              const float* __restrict__ bias, float* __restrict__ C) {
    extern __shared__ char sm[];
    gemm_body(A, W, bias, C, sm);
}

__global__ __launch_bounds__(256, 2)
void gemm_mma_qkv(const float* __restrict__ A,
                  const float* __restrict__ W0, const float* __restrict__ b0,
                  float* __restrict__ C0,
                  const float* __restrict__ W1, const float* __restrict__ b1,
                  float* __restrict__ C1,
                  const float* __restrict__ W2, const float* __restrict__ b2,
                  float* __restrict__ C2) {
    extern __shared__ char sm[];
    const float* W = (blockIdx.z == 0) ? W0 : (blockIdx.z == 1) ? W1 : W2;
    const float* b = (blockIdx.z == 0) ? b0 : (blockIdx.z == 1) ? b1 : b2;
    float* C = (blockIdx.z == 0) ? C0 : (blockIdx.z == 1) ? C1 : C2;
    gemm_body(A, W, b, C, sm);
}

// ===========================================================================
// Attention: FA2-style mma.sync fp16 split, occ 2.
// S = (Qh+Ql) K_h^T  (K lo dropped);  O += Ph Vt_h  (P lo + V lo dropped).
// Block: one (b,h) x 128 queries, 8 warps, 16 query rows/warp.
// smem: Qh/Ql/Kh [128][144B rows], Vth [64][272B rows]  -> 72704 B/CTA.
// ===========================================================================
#define SQH 0
#define SQL 18432
#define SKH 36864
#define SVH 55296
#define VTSTR 272
#define ATT_SMEM (SVH + 64 * VTSTR)   // 72704
#define QKSTR 144

__global__ __launch_bounds__(256, 2)
void attn_mma_kernel(const float* __restrict__ q, const float* __restrict__ k,
                     const float* __restrict__ v, float* __restrict__ ctx) {
    extern __shared__ char smc[];
    const int tid = threadIdx.x;
    const int wid = tid >> 5;
    const int lane = tid & 31;
    const int laneR = lane >> 2;
    const int laneC = lane & 3;
    const int b = blockIdx.x >> 4;
    const int h = blockIdx.x & 15;
    const int t0 = blockIdx.y * 128;
    const size_t base = (size_t)b * DIM + h * HD;
    const int mrow = wid * 16;

    // ---- load Q tile (128x64), split into Qh/Ql ----
#pragma unroll
    for (int it = 0; it < 8; it++) {
        int task = tid + it * 256;
        int row = task >> 4;
        int c = (task & 15) << 2;
        float4 f = *(const float4*)(q + (size_t)(t0 + row) * ROWSTR + base + c);
        float l0, l1, l2, l3;
        uint2 uh, ul;
        uh.x = pack_hi(f.x, f.y, l0, l1);
        uh.y = pack_hi(f.z, f.w, l2, l3);
        ul.x = pack2(l0, l1);
        ul.y = pack2(l2, l3);
        *(uint2*)(smc + SQH + row * QKSTR + c * 2) = uh;
        *(uint2*)(smc + SQL + row * QKSTR + c * 2) = ul;
    }

    float oacc[8][4];
#pragma unroll
    for (int i = 0; i < 8; i++)
#pragma unroll
        for (int r = 0; r < 4; r++) oacc[i][r] = 0.f;
    float mr[2] = {-1e30f, -1e30f};
    float ls[2] = {0.f, 0.f};

    for (int kt = 0; kt < 8; kt++) {
        const int s0 = kt * 128;
        __syncthreads();

        // ---- K tile (128x64), hi only ----
#pragma unroll
        for (int it = 0; it < 8; it++) {
            int task = tid + it * 256;
            int row = task >> 4;
            int c = (task & 15) << 2;
            float4 f = *(const float4*)(k + (size_t)(s0 + row) * ROWSTR + base + c);
            uint2 uh;
            uh.x = pack2(f.x, f.y);
            uh.y = pack2(f.z, f.w);
            *(uint2*)(smc + SKH + row * QKSTR + c * 2) = uh;
        }

        // ---- V tile transposed (hi only): Vt[d][s], s-pairs in u32 ----
#pragma unroll
        for (int it = 0; it < 4; it++) {
            int task = tid + it * 256;
            int sp = task >> 4;
            int d0 = (task & 15) << 2;
            const float* vp = v + (size_t)(s0 + 2 * sp) * ROWSTR + base + d0;
            float4 f0 = *(const float4*)vp;
            float4 f1 = *(const float4*)(vp + ROWSTR);
            float a0[4] = {f0.x, f0.y, f0.z, f0.w};
            float a1[4] = {f1.x, f1.y, f1.z, f1.w};
#pragma unroll
            for (int e = 0; e < 4; e++) {
                *(uint32_t*)(smc + SVH + (d0 + e) * VTSTR + sp * 4) =
                    pack2(a0[e], a1[e]);
            }
        }
        __syncthreads();

        // ---- S = Q K^T (16 rows x 128 keys), 2-pass split on Q ----
        float sacc[16][4];
#pragma unroll
        for (int nt = 0; nt < 16; nt++)
#pragma unroll
            for (int r = 0; r < 4; r++) sacc[nt][r] = 0.f;

#pragma unroll
        for (int ks = 0; ks < 4; ks++) {
            const uint32_t qb = (mrow + laneR) * QKSTR + ks * 32 + laneC * 4;
            uint32_t ah[4], al[4];
            ah[0] = *(const uint32_t*)(smc + SQH + qb);
            ah[1] = *(const uint32_t*)(smc + SQH + qb + 8 * QKSTR);
            ah[2] = *(const uint32_t*)(smc + SQH + qb + 16);
            ah[3] = *(const uint32_t*)(smc + SQH + qb + 8 * QKSTR + 16);
            al[0] = *(const uint32_t*)(smc + SQL + qb);
            al[1] = *(const uint32_t*)(smc + SQL + qb + 8 * QKSTR);
            al[2] = *(const uint32_t*)(smc + SQL + qb + 16);
            al[3] = *(const uint32_t*)(smc + SQL + qb + 8 * QKSTR + 16);
#pragma unroll
            for (int nt = 0; nt < 16; nt++) {
                const uint32_t kb =
                    (nt * 8 + laneR) * QKSTR + ks * 32 + laneC * 4;
                uint32_t bhf[2];
                bhf[0] = *(const uint32_t*)(smc + SKH + kb);
                bhf[1] = *(const uint32_t*)(smc + SKH + kb + 16);
                mma16816(sacc[nt], ah, bhf);
                mma16816(sacc[nt], al, bhf);
            }
        }

        // ---- online softmax ----
#pragma unroll
        for (int r = 0; r < 2; r++) {
            float mt = -1e30f;
#pragma unroll
            for (int nt = 0; nt < 16; nt++)
                mt = fmaxf(mt, fmaxf(sacc[nt][2 * r], sacc[nt][2 * r + 1]));
            mt = fmaxf(mt, __shfl_xor_sync(0xffffffffu, mt, 1));
            mt = fmaxf(mt, __shfl_xor_sync(0xffffffffu, mt, 2));
            float mnew = fmaxf(mr[r], mt);
            float corr = __expf((mr[r] - mnew) * 0.125f);
            mr[r] = mnew;
            const float mm = mnew * 0.125f;
            float rs = 0.f;
#pragma unroll
            for (int nt = 0; nt < 16; nt++) {
                float p0 = __expf(fmaf(sacc[nt][2 * r], 0.125f, -mm));
                float p1 = __expf(fmaf(sacc[nt][2 * r + 1], 0.125f, -mm));
                sacc[nt][2 * r] = p0;
                sacc[nt][2 * r + 1] = p1;
                rs += p0 + p1;
            }
            rs += __shfl_xor_sync(0xffffffffu, rs, 1);
            rs += __shfl_xor_sync(0xffffffffu, rs, 2);
            ls[r] = ls[r] * corr + rs;
#pragma unroll
            for (int nt2 = 0; nt2 < 8; nt2++) {
                oacc[nt2][2 * r] *= corr;
                oacc[nt2][2 * r + 1] *= corr;
            }
        }

        // ---- O += P @ V (P hi only, V hi only: single pass) ----
#pragma unroll
        for (int j = 0; j < 8; j++) {
            uint32_t ph[4];
            ph[0] = pack2(sacc[2 * j][0], sacc[2 * j][1]);
            ph[1] = pack2(sacc[2 * j][2], sacc[2 * j][3]);
            ph[2] = pack2(sacc[2 * j + 1][0], sacc[2 * j + 1][1]);
            ph[3] = pack2(sacc[2 * j + 1][2], sacc[2 * j + 1][3]);
#pragma unroll
            for (int nt2 = 0; nt2 < 8; nt2++) {
                const uint32_t vb =
                    (nt2 * 8 + laneR) * VTSTR + j * 32 + laneC * 4;
                uint32_t vhf[2];
                vhf[0] = *(const uint32_t*)(smc + SVH + vb);
                vhf[1] = *(const uint32_t*)(smc + SVH + vb + 16);
                mma16816(oacc[nt2], ph, vhf);
            }
        }
    }

    // ---- normalize and store ----
    const float inv0 = 1.f / ls[0];
    const float inv1 = 1.f / ls[1];
    const int r0 = t0 + mrow + laneR;
#pragma unroll
    for (int nt2 = 0; nt2 < 8; nt2++) {
        const size_t col = base + nt2 * 8 + laneC * 2;
        *(float2*)(ctx + (size_t)r0 * ROWSTR + col) =
            make_float2(oacc[nt2][0] * inv0, oacc[nt2][1] * inv0);
        *(float2*)(ctx + (size_t)(r0 + 8) * ROWSTR + col) =
            make_float2(oacc[nt2][2] * inv1, oacc[nt2][3] * inv1);
    }
}

// ===========================================================================
// Fused residual-add + LayerNorm over rows of 1024. One block per row.
// ===========================================================================
__global__ __launch_bounds__(256)
void add_ln_kernel(const float* __restrict__ a, const float* __restrict__ res,
                   const float* __restrict__ gma, const float* __restrict__ bta,
                   float* __restrict__ out) {
    __shared__ float red[16];
    const int row = blockIdx.x;
    const int tid = threadIdx.x;

    float4 va = *(const float4*)(a + (size_t)row * DIM + tid * 4);
    float4 vr = *(const float4*)(res + (size_t)row * DIM + tid * 4);
    float4 x;
    x.x = va.x + vr.x; x.y = va.y + vr.y; x.z = va.z + vr.z; x.w = va.w + vr.w;

    float sum = x.x + x.y + x.z + x.w;
    float sq = x.x * x.x + x.y * x.y + x.z * x.z + x.w * x.w;
#pragma unroll
    for (int d = 16; d; d >>= 1) {
        sum += __shfl_xor_sync(0xffffffffu, sum, d);
        sq += __shfl_xor_sync(0xffffffffu, sq, d);
    }
    const int warp = tid >> 5;
    if ((tid & 31) == 0) { red[warp] = sum; red[8 + warp] = sq; }
    __syncthreads();
    if (tid < 32) {
        float s = (tid < 8) ? red[tid] : 0.f;
        float q2 = (tid < 8) ? red[8 + tid] : 0.f;
#pragma unroll
        for (int d = 4; d; d >>= 1) {
            s += __shfl_xor_sync(0xffffffffu, s, d);
            q2 += __shfl_xor_sync(0xffffffffu, q2, d);
        }
        if (tid == 0) { red[0] = s; red[1] = q2; }
    }
    __syncthreads();
    const float mean = red[0] * (1.f / DIM);
    const float var = red[1] * (1.f / DIM) - mean * mean;
    const float rstd = rsqrtf(var + 1e-5f);

    float4 g4 = *(const float4*)(gma + tid * 4);
    float4 b4 = *(const float4*)(bta + tid * 4);
    float4 o;
    o.x = (x.x - mean) * rstd * g4.x + b4.x;
    o.y = (x.y - mean) * rstd * g4.y + b4.y;
    o.z = (x.z - mean) * rstd * g4.z + b4.z;
    o.w = (x.w - mean) * rstd * g4.w + b4.w;
    *(float4*)(out + (size_t)row * DIM + tid * 4) = o;
}

// ===========================================================================
// launch
// ===========================================================================
extern "C" void kernel_launch(void* const* d_in, const int* in_sizes, int n_in,
                              void* d_out, int out_size) {
    const float* x  = (const float*)d_in[0];
    const float* Wq = (const float*)d_in[1];
    const float* bq = (const float*)d_in[2];
    const float* Wk = (const float*)d_in[3];
    const float* bk = (const float*)d_in[4];
    const float* Wv = (const float*)d_in[5];
    const float* bv = (const float*)d_in[6];
    const float* Wo = (const float*)d_in[7];
    const float* bo = (const float*)d_in[8];
    const float* Wl = (const float*)d_in[9];
    const float* bl = (const float*)d_in[10];
    const float* g1 = (const float*)d_in[11];
    const float* b1 = (const float*)d_in[12];
    const float* g2 = (const float*)d_in[13];
    const float* b2 = (const float*)d_in[14];
    float* out = (float*)d_out;

    float *q, *k, *v, *ctx, *t1, *hh, *t2;
    cudaGetSymbolAddress((void**)&q, g_q);
    cudaGetSymbolAddress((void**)&k, g_k);
    cudaGetSymbolAddress((void**)&v, g_v);
    cudaGetSymbolAddress((void**)&ctx, g_ctx);
    cudaGetSymbolAddress((void**)&t1, g_t1);
    cudaGetSymbolAddress((void**)&hh, g_h);
    cudaGetSymbolAddress((void**)&t2, g_t2);

    cudaFuncSetAttribute(attn_mma_kernel,
                         cudaFuncAttributeMaxDynamicSharedMemorySize, ATT_SMEM);
    cudaFuncSetAttribute(gemm_mma,
                         cudaFuncAttributeMaxDynamicSharedMemorySize, GEMM_SMEM);
    cudaFuncSetAttribute(gemm_mma_qkv,
                         cudaFuncAttributeMaxDynamicSharedMemorySize, GEMM_SMEM);

    dim3 ggrid(DIM / 128, NTOK / 128);      // (8, 32)
    dim3 ggrid3(DIM / 128, NTOK / 128, 3);  // QKV batched
    dim3 gblk(256);

    gemm_mma_qkv<<<ggrid3, gblk, GEMM_SMEM>>>(x, Wq, bq, q, Wk, bk, k, Wv, bv, v);
    attn_mma_kernel<<<dim3(BB * NH, TT / 128), 256, ATT_SMEM>>>(q, k, v, ctx);
    gemm_mma<<<ggrid, gblk, GEMM_SMEM>>>(ctx, Wo, bo, t1);
    add_ln_kernel<<<NTOK, 256>>>(t1, x, g1, b1, hh);
    gemm_mma<<<ggrid, gblk, GEMM_SMEM>>>(hh, Wl, bl, t2);
    add_ln_kernel<<<NTOK, 256>>>(t2, hh, g2, b2, out);
}